// round 10
// baseline (speedup 1.0000x reference)
#include <cuda_runtime.h>
#include <cuda_fp16.h>

#define NU 100000
#define NI 50000
#define NN 150000            // NU + NI
#define NE 3000000
#define DIM 128
#define D4  32               // DIM / 4 (float4 / uint2 chunks per row)

#define SCAN_B 1024
#define SCAN_NB 147          // ceil(NN / 1024)

#define INIT_BLOCKS 2048
#define HIST_BLOCKS 2048

// ---- device scratch (allocation-free requirement) ----
// fp16 embedding buffers: [0]=x, [1]=a1, [2]=a2. (a3 is fused into output.)
__device__ uint2 g_h[3][(size_t)NN * D4];
__device__ int    g_deg[NN];
__device__ float  g_inv[NN];
__device__ int    g_off[NN];
__device__ int    g_cur[NN];
__device__ int    g_csr[NE];
__device__ int    g_total;
__device__ int    g_is64;

__device__ __forceinline__ __half2 u2h(unsigned u) {
    return *reinterpret_cast<__half2*>(&u);
}

// ---- 0) fused: detect edge dtype (block 0) + zero degree array + counter ----
__global__ void k_detect_zero(const int* __restrict__ ei32) {
    int i = blockIdx.x * blockDim.x + threadIdx.x;
    if (i < NN) g_deg[i] = 0;
    if (i == 0) g_total = 0;
    if (blockIdx.x == 0) {
        __shared__ int s_or[256];
        int acc = 0;
        for (int j = threadIdx.x; j < 4096; j += 256) acc |= ei32[2 * j + 1];
        s_or[threadIdx.x] = acc;
        __syncthreads();
        for (int d = 128; d > 0; d >>= 1) {
            if (threadIdx.x < d) s_or[threadIdx.x] |= s_or[threadIdx.x + d];
            __syncthreads();
        }
        if (threadIdx.x == 0) g_is64 = (s_or[0] == 0) ? 1 : 0;
    }
}

// ---- 1) fused: init fp16 embeddings (blocks [0,INIT)) + dst histogram (rest) ----
__global__ void k_init_hist(const float4* __restrict__ u4,
                            const float4* __restrict__ i4,
                            const void* __restrict__ ei) {
    if (blockIdx.x < INIT_BLOCKS) {
        const int n4 = NN * D4;
        const int u_n4 = NU * D4;
        const int stride = INIT_BLOCKS * blockDim.x;
        for (int i = blockIdx.x * blockDim.x + threadIdx.x; i < n4; i += stride) {
            float4 v = (i < u_n4) ? u4[i] : i4[i - u_n4];
            __half2 a = __floats2half2_rn(v.x, v.y);
            __half2 b = __floats2half2_rn(v.z, v.w);
            uint2 o;
            o.x = *reinterpret_cast<unsigned*>(&a);
            o.y = *reinterpret_cast<unsigned*>(&b);
            g_h[0][i] = o;
        }
    } else {
        const int T = (gridDim.x - INIT_BLOCKS) * blockDim.x;
        int t = (blockIdx.x - INIT_BLOCKS) * blockDim.x + threadIdx.x;
        if (g_is64) {
            const longlong2* d2 =
                (const longlong2*)((const long long*)ei + NE);
            for (int i = t; i < NE / 2; i += T) {
                longlong2 v = d2[i];
                int d0 = (int)v.x, d1 = (int)v.y;
                if ((unsigned)d0 < NN) atomicAdd(&g_deg[d0], 1);
                if ((unsigned)d1 < NN) atomicAdd(&g_deg[d1], 1);
            }
        } else {
            const int4* d4 = (const int4*)((const int*)ei + NE);
            for (int i = t; i < NE / 4; i += T) {
                int4 v = d4[i];
                if ((unsigned)v.x < NN) atomicAdd(&g_deg[v.x], 1);
                if ((unsigned)v.y < NN) atomicAdd(&g_deg[v.y], 1);
                if ((unsigned)v.z < NN) atomicAdd(&g_deg[v.z], 1);
                if ((unsigned)v.w < NN) atomicAdd(&g_deg[v.w], 1);
            }
        }
    }
}

// ---- 2) single-kernel offsets: block-local scan + atomic block base.
//         CSR rows get disjoint ranges; global order is irrelevant. ----
__global__ void k_offsets() {
    __shared__ int sh[SCAN_B];
    __shared__ int s_base;
    int gid = blockIdx.x * SCAN_B + threadIdx.x;
    int v = (gid < NN) ? g_deg[gid] : 0;
    sh[threadIdx.x] = v;
    __syncthreads();
    for (int d = 1; d < SCAN_B; d <<= 1) {
        int t = (threadIdx.x >= d) ? sh[threadIdx.x - d] : 0;
        __syncthreads();
        sh[threadIdx.x] += t;
        __syncthreads();
    }
    if (threadIdx.x == SCAN_B - 1)
        s_base = atomicAdd(&g_total, sh[SCAN_B - 1]);
    __syncthreads();
    if (gid < NN) {
        int o = s_base + sh[threadIdx.x] - v;   // block-exclusive + base
        g_off[gid] = o;
        g_cur[gid] = o;
        g_inv[gid] = (v > 0) ? (1.0f / (float)v) : 0.0f;
    }
}

// ---- 3) scatter src indices into CSR slots (vectorized 2-edge loads) ----
__global__ void k_scatter(const void* __restrict__ ei) {
    const int T = gridDim.x * blockDim.x;
    int t = blockIdx.x * blockDim.x + threadIdx.x;
    if (g_is64) {
        const longlong2* s2 = (const longlong2*)ei;
        const longlong2* d2 = (const longlong2*)((const long long*)ei + NE);
        for (int i = t; i < NE / 2; i += T) {
            longlong2 sv = s2[i];
            longlong2 dv = d2[i];
            int s0 = (int)sv.x, d0 = (int)dv.x;
            int s1 = (int)sv.y, d1 = (int)dv.y;
            if ((unsigned)d0 < NN && (unsigned)s0 < NN)
                g_csr[atomicAdd(&g_cur[d0], 1)] = s0;
            if ((unsigned)d1 < NN && (unsigned)s1 < NN)
                g_csr[atomicAdd(&g_cur[d1], 1)] = s1;
        }
    } else {
        const int2* s2 = (const int2*)ei;
        const int2* d2 = (const int2*)((const int*)ei + NE);
        for (int i = t; i < NE / 2; i += T) {
            int2 sv = s2[i];
            int2 dv = d2[i];
            if ((unsigned)dv.x < NN && (unsigned)sv.x < NN)
                g_csr[atomicAdd(&g_cur[dv.x], 1)] = sv.x;
            if ((unsigned)dv.y < NN && (unsigned)sv.y < NN)
                g_csr[atomicAdd(&g_cur[dv.y], 1)] = sv.y;
        }
    }
}

// ---- helper: accumulate one fp16 chunk (4 halves) into fp32 sums ----
__device__ __forceinline__ void acc4(uint2 v, float& sx, float& sy,
                                     float& sz, float& sw) {
    float2 fa = __half22float2(u2h(v.x));
    float2 fb = __half22float2(u2h(v.y));
    sx += fa.x; sy += fa.y; sz += fb.x; sw += fb.y;
}

// ---- 4) propagation layer. FUSE=1: layer 3 + final combine fused.
//         Warp per node, lane handles 4 dims. Depth-2 HADD2 tree per 4 edges. ----
template<int FUSE>
__global__ void k_layer_t(int in_idx,
                          const float4* __restrict__ u4,
                          const float4* __restrict__ i4,
                          float4* __restrict__ out4) {
    const uint2* __restrict__ in = g_h[in_idx];

    int warp = (blockIdx.x * blockDim.x + threadIdx.x) >> 5;
    if (warp >= NN) return;
    int lane = threadIdx.x & 31;

    int beg = g_off[warp];
    int end = beg + g_deg[warp];   // offsets are per-block based; deg gives the row end

    float sx = 0.f, sy = 0.f, sz = 0.f, sw = 0.f;
    int e = beg;
    for (; e + 3 < end; e += 4) {
        int s0 = g_csr[e];
        int s1 = g_csr[e + 1];
        int s2 = g_csr[e + 2];
        int s3 = g_csr[e + 3];
        uint2 v0 = in[(size_t)s0 * D4 + lane];
        uint2 v1 = in[(size_t)s1 * D4 + lane];
        uint2 v2 = in[(size_t)s2 * D4 + lane];
        uint2 v3 = in[(size_t)s3 * D4 + lane];
        // depth-2 fp16 tree, one fp32 accumulate per 4 edges
        __half2 a = __hadd2(__hadd2(u2h(v0.x), u2h(v1.x)),
                            __hadd2(u2h(v2.x), u2h(v3.x)));
        __half2 b = __hadd2(__hadd2(u2h(v0.y), u2h(v1.y)),
                            __hadd2(u2h(v2.y), u2h(v3.y)));
        float2 fa = __half22float2(a);
        float2 fb = __half22float2(b);
        sx += fa.x; sy += fa.y; sz += fb.x; sw += fb.y;
    }
    for (; e < end; ++e) {                      // tail: exact fp32 adds
        int s = g_csr[e];
        acc4(in[(size_t)s * D4 + lane], sx, sy, sz, sw);
    }

    float idg = g_inv[warp];
    float rx = sx * idg, ry = sy * idg, rz = sz * idg, rw = sw * idg;

    size_t oi = (size_t)warp * D4 + lane;
    if (FUSE) {
        // out = (x + a1 + a2 + a3) / 4 ; a2 row == in[oi], a3 == r (registers)
        float4 x = (warp < NU) ? u4[oi] : i4[oi - (size_t)NU * D4];
        float tx = x.x + rx, ty = x.y + ry, tz = x.z + rz, tw = x.w + rw;
        acc4(g_h[1][oi], tx, ty, tz, tw);
        acc4(in[oi],     tx, ty, tz, tw);
        float4 r;
        r.x = tx * 0.25f; r.y = ty * 0.25f; r.z = tz * 0.25f; r.w = tw * 0.25f;
        out4[oi] = r;
    } else {
        __half2 ha = __floats2half2_rn(rx, ry);
        __half2 hb = __floats2half2_rn(rz, rw);
        uint2 o;
        o.x = *reinterpret_cast<unsigned*>(&ha);
        o.y = *reinterpret_cast<unsigned*>(&hb);
        g_h[in_idx + 1][oi] = o;
    }
}

extern "C" void kernel_launch(void* const* d_in, const int* in_sizes, int n_in,
                              void* d_out, int out_size) {
    const float4* u4  = (const float4*)d_in[0];
    const float4* i4  = (const float4*)d_in[1];
    const void*   ei  = d_in[2];
    float4*       out = (float4*)d_out;

    // CSR build: detect+zero, fused init+hist, one-shot offsets, scatter
    k_detect_zero<<<(NN + 255) / 256, 256>>>((const int*)ei);
    k_init_hist<<<INIT_BLOCKS + HIST_BLOCKS, 256>>>(u4, i4, ei);
    k_offsets<<<SCAN_NB, SCAN_B>>>();
    k_scatter<<<2048, 256>>>(ei);

    // 3 propagation layers (warp per node); layer 3 fused with final combine
    const int layer_blocks = (NN * 32 + 255) / 256;
    k_layer_t<0><<<layer_blocks, 256>>>(0, u4, i4, out);  // x  -> a1
    k_layer_t<0><<<layer_blocks, 256>>>(1, u4, i4, out);  // a1 -> a2
    k_layer_t<1><<<layer_blocks, 256>>>(2, u4, i4, out);  // a2 -> out (fused)
}

// round 11
// speedup vs baseline: 1.1654x; 1.1654x over previous
#include <cuda_runtime.h>
#include <cuda_fp16.h>

#define NU 100000
#define NI 50000
#define NN 150000            // NU + NI
#define NE 3000000
#define DIM 128
#define D4  32               // DIM / 4 (float4 / uint2 chunks per row)

#define SCAN_B 1024
#define SCAN_NB 147          // ceil(NN / 1024)

// ---- device scratch (allocation-free requirement) ----
// fp16 embedding buffers: [0]=x, [1]=a1, [2]=a2. (a3 is fused into output.)
__device__ uint2 g_h[3][(size_t)NN * D4];
__device__ int    g_deg[NN];
__device__ float  g_inv[NN];
__device__ int    g_off[NN + 1];
__device__ int    g_cur[NN];
__device__ int    g_csr[NE];
__device__ int    g_part[SCAN_NB];
__device__ int    g_is64;

__device__ __forceinline__ __half2 u2h(unsigned u) {
    return *reinterpret_cast<__half2*>(&u);
}

// ---- 0a) detect edge_index element width: int64 stores high word = 0 ----
__global__ void k_detect(const int* __restrict__ ei32) {
    __shared__ int s_or[256];
    int acc = 0;
    for (int i = threadIdx.x; i < 4096; i += 256) acc |= ei32[2 * i + 1];
    s_or[threadIdx.x] = acc;
    __syncthreads();
    for (int d = 128; d > 0; d >>= 1) {
        if (threadIdx.x < d) s_or[threadIdx.x] |= s_or[threadIdx.x + d];
        __syncthreads();
    }
    if (threadIdx.x == 0) g_is64 = (s_or[0] == 0) ? 1 : 0;
}

__device__ __forceinline__ void load_edge(const void* ei, int is64, int e,
                                          int& src, int& dst) {
    if (is64) {
        src = (int)((const long long*)ei)[e];
        dst = (int)((const long long*)ei)[NE + e];
    } else {
        src = ((const int*)ei)[e];
        dst = ((const int*)ei)[NE + e];
    }
}

// ---- 0b) zero degree array ----
__global__ void k_zero_deg() {
    int i = blockIdx.x * blockDim.x + threadIdx.x;
    if (i < NN) g_deg[i] = 0;
}

// ---- 1) init: g_h[0] = fp16(cat(user, item)) ----
__global__ void k_init_emb(const float4* __restrict__ u4,
                           const float4* __restrict__ i4) {
    const int n4 = NN * D4;
    const int u_n4 = NU * D4;
    for (int i = blockIdx.x * blockDim.x + threadIdx.x; i < n4;
         i += gridDim.x * blockDim.x) {
        float4 v = (i < u_n4) ? u4[i] : i4[i - u_n4];
        __half2 a = __floats2half2_rn(v.x, v.y);
        __half2 b = __floats2half2_rn(v.z, v.w);
        uint2 o;
        o.x = *reinterpret_cast<unsigned*>(&a);
        o.y = *reinterpret_cast<unsigned*>(&b);
        g_h[0][i] = o;
    }
}

// ---- 2) degree histogram over dst (dst-only reads, unroll x2) ----
__global__ void k_hist(const void* __restrict__ ei) {
    const int is64 = g_is64;
    const int T = gridDim.x * blockDim.x;
    int e = blockIdx.x * blockDim.x + threadIdx.x;
    if (is64) {
        const long long* d64 = (const long long*)ei + NE;
        for (; e + T < NE; e += 2 * T) {
            int d0 = (int)d64[e];
            int d1 = (int)d64[e + T];
            if ((unsigned)d0 < NN) atomicAdd(&g_deg[d0], 1);
            if ((unsigned)d1 < NN) atomicAdd(&g_deg[d1], 1);
        }
        for (; e < NE; e += T) {
            int d0 = (int)d64[e];
            if ((unsigned)d0 < NN) atomicAdd(&g_deg[d0], 1);
        }
    } else {
        const int* d32 = (const int*)ei + NE;
        for (; e + T < NE; e += 2 * T) {
            int d0 = d32[e];
            int d1 = d32[e + T];
            if ((unsigned)d0 < NN) atomicAdd(&g_deg[d0], 1);
            if ((unsigned)d1 < NN) atomicAdd(&g_deg[d1], 1);
        }
        for (; e < NE; e += T) {
            int d0 = d32[e];
            if ((unsigned)d0 < NN) atomicAdd(&g_deg[d0], 1);
        }
    }
}

// ---- 3a) block-local exclusive scan of deg -> g_off, block sums -> g_part ----
__global__ void k_scan1() {
    __shared__ int sh[SCAN_B];
    int gid = blockIdx.x * SCAN_B + threadIdx.x;
    int v = (gid < NN) ? g_deg[gid] : 0;
    sh[threadIdx.x] = v;
    __syncthreads();
    for (int d = 1; d < SCAN_B; d <<= 1) {
        int t = (threadIdx.x >= d) ? sh[threadIdx.x - d] : 0;
        __syncthreads();
        sh[threadIdx.x] += t;
        __syncthreads();
    }
    int incl = sh[threadIdx.x];
    if (gid < NN) g_off[gid] = incl - v;          // exclusive
    if (threadIdx.x == SCAN_B - 1) g_part[blockIdx.x] = incl;
}

// ---- 3b) single-block exclusive scan of block sums ----
__global__ void k_scan2() {
    __shared__ int sh[256];
    int tid = threadIdx.x;
    int v = (tid < SCAN_NB) ? g_part[tid] : 0;
    sh[tid] = v;
    __syncthreads();
    for (int d = 1; d < 256; d <<= 1) {
        int t = (tid >= d) ? sh[tid - d] : 0;
        __syncthreads();
        sh[tid] += t;
        __syncthreads();
    }
    if (tid < SCAN_NB) g_part[tid] = sh[tid] - v; // exclusive
}

// ---- 3c) add block offsets, init cursor, compute inv_deg ----
__global__ void k_scan3() {
    int gid = blockIdx.x * SCAN_B + threadIdx.x;
    if (gid < NN) {
        int o = g_off[gid] + g_part[blockIdx.x];
        g_off[gid] = o;
        g_cur[gid] = o;
        int d = g_deg[gid];
        g_inv[gid] = (d > 0) ? (1.0f / (float)d) : 0.0f;
    }
    if (gid == 0) g_off[NN] = NE;
}

// ---- 4) scatter src indices into CSR slots ----
__global__ void k_scatter(const void* __restrict__ ei) {
    const int is64 = g_is64;
    for (int e = blockIdx.x * blockDim.x + threadIdx.x; e < NE;
         e += gridDim.x * blockDim.x) {
        int src, dst;
        load_edge(ei, is64, e, src, dst);
        if ((unsigned)dst < NN && (unsigned)src < NN) {
            int pos = atomicAdd(&g_cur[dst], 1);
            g_csr[pos] = src;
        }
    }
}

// ---- helper: accumulate one fp16 chunk (4 halves) into fp32 sums ----
__device__ __forceinline__ void acc4(uint2 v, float& sx, float& sy,
                                     float& sz, float& sw) {
    float2 fa = __half22float2(u2h(v.x));
    float2 fb = __half22float2(u2h(v.y));
    sx += fa.x; sy += fa.y; sz += fb.x; sw += fb.y;
}

// ---- 5) propagation layer. FUSE=1: layer 3 + final combine fused.
//         Warp per node, lane handles 4 dims. Depth-2 HADD2 tree per 4 edges. ----
template<int FUSE>
__global__ void k_layer_t(int in_idx, float4* __restrict__ out4) {
    const uint2* __restrict__ in = g_h[in_idx];

    int warp = (blockIdx.x * blockDim.x + threadIdx.x) >> 5;
    if (warp >= NN) return;
    int lane = threadIdx.x & 31;

    int beg = g_off[warp];
    int end = g_off[warp + 1];

    float sx = 0.f, sy = 0.f, sz = 0.f, sw = 0.f;
    int e = beg;
    for (; e + 3 < end; e += 4) {
        int s0 = g_csr[e];
        int s1 = g_csr[e + 1];
        int s2 = g_csr[e + 2];
        int s3 = g_csr[e + 3];
        uint2 v0 = in[(size_t)s0 * D4 + lane];
        uint2 v1 = in[(size_t)s1 * D4 + lane];
        uint2 v2 = in[(size_t)s2 * D4 + lane];
        uint2 v3 = in[(size_t)s3 * D4 + lane];
        // depth-2 fp16 tree, one fp32 accumulate per 4 edges
        __half2 a = __hadd2(__hadd2(u2h(v0.x), u2h(v1.x)),
                            __hadd2(u2h(v2.x), u2h(v3.x)));
        __half2 b = __hadd2(__hadd2(u2h(v0.y), u2h(v1.y)),
                            __hadd2(u2h(v2.y), u2h(v3.y)));
        float2 fa = __half22float2(a);
        float2 fb = __half22float2(b);
        sx += fa.x; sy += fa.y; sz += fb.x; sw += fb.y;
    }
    for (; e < end; ++e) {                      // tail: exact fp32 adds
        int s = g_csr[e];
        acc4(in[(size_t)s * D4 + lane], sx, sy, sz, sw);
    }

    float idg = g_inv[warp];
    float rx = sx * idg, ry = sy * idg, rz = sz * idg, rw = sw * idg;

    size_t oi = (size_t)warp * D4 + lane;
    if (FUSE) {
        // out = (x + a1 + a2 + a3) / 4 ; x from fp16 g_h[0], a2 == in[oi],
        // a3 == r (registers). All fp16 reads, fp32 accumulate.
        float tx = rx, ty = ry, tz = rz, tw = rw;
        acc4(g_h[0][oi], tx, ty, tz, tw);
        acc4(g_h[1][oi], tx, ty, tz, tw);
        acc4(in[oi],     tx, ty, tz, tw);
        float4 r;
        r.x = tx * 0.25f; r.y = ty * 0.25f; r.z = tz * 0.25f; r.w = tw * 0.25f;
        out4[oi] = r;
    } else {
        __half2 ha = __floats2half2_rn(rx, ry);
        __half2 hb = __floats2half2_rn(rz, rw);
        uint2 o;
        o.x = *reinterpret_cast<unsigned*>(&ha);
        o.y = *reinterpret_cast<unsigned*>(&hb);
        g_h[in_idx + 1][oi] = o;
    }
}

extern "C" void kernel_launch(void* const* d_in, const int* in_sizes, int n_in,
                              void* d_out, int out_size) {
    const float4* u4  = (const float4*)d_in[0];
    const float4* i4  = (const float4*)d_in[1];
    const void*   ei  = d_in[2];
    float4*       out = (float4*)d_out;

    // dtype detection + CSR build
    k_detect<<<1, 256>>>((const int*)ei);
    k_zero_deg<<<(NN + 255) / 256, 256>>>();
    k_init_emb<<<2048, 256>>>(u4, i4);
    k_hist<<<4096, 256>>>(ei);
    k_scan1<<<SCAN_NB, SCAN_B>>>();
    k_scan2<<<1, 256>>>();
    k_scan3<<<SCAN_NB, SCAN_B>>>();
    k_scatter<<<2048, 256>>>(ei);

    // 3 propagation layers (warp per node); layer 3 fused with final combine
    const int layer_blocks = (NN * 32 + 255) / 256;
    k_layer_t<0><<<layer_blocks, 256>>>(0, out);  // x  -> a1
    k_layer_t<0><<<layer_blocks, 256>>>(1, out);  // a1 -> a2
    k_layer_t<1><<<layer_blocks, 256>>>(2, out);  // a2 -> out (fused)
}

// round 12
// speedup vs baseline: 1.1661x; 1.0006x over previous
#include <cuda_runtime.h>
#include <cuda_fp16.h>

#define NU 100000
#define NI 50000
#define NN 150000            // NU + NI
#define NE 3000000
#define DIM 128
#define D4  32               // DIM / 4 (float4 / uint2 chunks per row)

#define SCAN_B 1024
#define SCAN_NB 147          // ceil(NN / 1024) — all blocks co-resident on 148 SMs

// ---- device scratch (allocation-free requirement) ----
// fp16 embedding buffers: [0]=x, [1]=a1, [2]=a2. (a3 is fused into output.)
__device__ uint2 g_h[3][(size_t)NN * D4];
__device__ int    g_deg[NN];
__device__ float  g_inv[NN];
__device__ int    g_off[NN + 1];
__device__ int    g_cur[NN];
__device__ int    g_csr[NE];
__device__ int    g_part[SCAN_NB];
__device__ int    g_base[SCAN_NB];
__device__ int    g_done;
__device__ int    g_ready;
__device__ int    g_is64;

__device__ __forceinline__ __half2 u2h(unsigned u) {
    return *reinterpret_cast<__half2*>(&u);
}

// ---- 0) fused: detect edge dtype (block 0) + zero deg + reset scan flags ----
__global__ void k_detect_zero(const int* __restrict__ ei32) {
    int i = blockIdx.x * blockDim.x + threadIdx.x;
    if (i < NN) g_deg[i] = 0;
    if (i == 0) { g_done = 0; g_ready = 0; }
    if (blockIdx.x == 0) {
        __shared__ int s_or[256];
        int acc = 0;
        for (int j = threadIdx.x; j < 4096; j += 256) acc |= ei32[2 * j + 1];
        s_or[threadIdx.x] = acc;
        __syncthreads();
        for (int d = 128; d > 0; d >>= 1) {
            if (threadIdx.x < d) s_or[threadIdx.x] |= s_or[threadIdx.x + d];
            __syncthreads();
        }
        if (threadIdx.x == 0) g_is64 = (s_or[0] == 0) ? 1 : 0;
    }
}

__device__ __forceinline__ void load_edge(const void* ei, int is64, int e,
                                          int& src, int& dst) {
    if (is64) {
        src = (int)((const long long*)ei)[e];
        dst = (int)((const long long*)ei)[NE + e];
    } else {
        src = ((const int*)ei)[e];
        dst = ((const int*)ei)[NE + e];
    }
}

// ---- 1) init: g_h[0] = fp16(cat(user, item)) ----
__global__ void k_init_emb(const float4* __restrict__ u4,
                           const float4* __restrict__ i4) {
    const int n4 = NN * D4;
    const int u_n4 = NU * D4;
    for (int i = blockIdx.x * blockDim.x + threadIdx.x; i < n4;
         i += gridDim.x * blockDim.x) {
        float4 v = (i < u_n4) ? u4[i] : i4[i - u_n4];
        __half2 a = __floats2half2_rn(v.x, v.y);
        __half2 b = __floats2half2_rn(v.z, v.w);
        uint2 o;
        o.x = *reinterpret_cast<unsigned*>(&a);
        o.y = *reinterpret_cast<unsigned*>(&b);
        g_h[0][i] = o;
    }
}

// ---- 2) degree histogram over dst (dst-only reads, unroll x2) ----
__global__ void k_hist(const void* __restrict__ ei) {
    const int is64 = g_is64;
    const int T = gridDim.x * blockDim.x;
    int e = blockIdx.x * blockDim.x + threadIdx.x;
    if (is64) {
        const long long* d64 = (const long long*)ei + NE;
        for (; e + T < NE; e += 2 * T) {
            int d0 = (int)d64[e];
            int d1 = (int)d64[e + T];
            if ((unsigned)d0 < NN) atomicAdd(&g_deg[d0], 1);
            if ((unsigned)d1 < NN) atomicAdd(&g_deg[d1], 1);
        }
        for (; e < NE; e += T) {
            int d0 = (int)d64[e];
            if ((unsigned)d0 < NN) atomicAdd(&g_deg[d0], 1);
        }
    } else {
        const int* d32 = (const int*)ei + NE;
        for (; e + T < NE; e += 2 * T) {
            int d0 = d32[e];
            int d1 = d32[e + T];
            if ((unsigned)d0 < NN) atomicAdd(&g_deg[d0], 1);
            if ((unsigned)d1 < NN) atomicAdd(&g_deg[d1], 1);
        }
        for (; e < NE; e += T) {
            int d0 = d32[e];
            if ((unsigned)d0 < NN) atomicAdd(&g_deg[d0], 1);
        }
    }
}

// ---- 3) single-kernel ordered exclusive scan (147 co-resident blocks).
//         Last-arriving block scans the partials; others spin on ready flag. ----
__global__ void k_scan_fused() {
    __shared__ int sh[SCAN_B];
    __shared__ int s_last;
    __shared__ int s_base;
    int bid = blockIdx.x;
    int gid = bid * SCAN_B + threadIdx.x;
    int v = (gid < NN) ? g_deg[gid] : 0;
    sh[threadIdx.x] = v;
    __syncthreads();
    for (int d = 1; d < SCAN_B; d <<= 1) {
        int t = (threadIdx.x >= d) ? sh[threadIdx.x - d] : 0;
        __syncthreads();
        sh[threadIdx.x] += t;
        __syncthreads();
    }
    int incl = sh[threadIdx.x];                   // keep in register (sh reused below)
    if (threadIdx.x == 0) {
        g_part[bid] = sh[SCAN_B - 1];
        __threadfence();
        s_last = (atomicAdd(&g_done, 1) == SCAN_NB - 1) ? 1 : 0;
    }
    __syncthreads();
    if (s_last) {
        // block-wide exclusive scan of the 147 block sums
        int pv = (threadIdx.x < SCAN_NB) ? g_part[threadIdx.x] : 0;
        sh[threadIdx.x] = pv;
        __syncthreads();
        for (int d = 1; d < SCAN_B; d <<= 1) {
            int t = (threadIdx.x >= d) ? sh[threadIdx.x - d] : 0;
            __syncthreads();
            sh[threadIdx.x] += t;
            __syncthreads();
        }
        if (threadIdx.x < SCAN_NB) g_base[threadIdx.x] = sh[threadIdx.x] - pv;
        __threadfence();
        if (threadIdx.x == 0) atomicExch(&g_ready, 1);
    }
    if (threadIdx.x == 0) {
        while (atomicAdd(&g_ready, 0) == 0) { }
        s_base = g_base[bid];
    }
    __syncthreads();
    if (gid < NN) {
        int o = s_base + incl - v;                // ordered exclusive offset
        g_off[gid] = o;
        g_cur[gid] = o;
        g_inv[gid] = (v > 0) ? (1.0f / (float)v) : 0.0f;
    }
    if (gid == 0) g_off[NN] = NE;
}

// ---- 4) scatter src indices into CSR slots ----
__global__ void k_scatter(const void* __restrict__ ei) {
    const int is64 = g_is64;
    for (int e = blockIdx.x * blockDim.x + threadIdx.x; e < NE;
         e += gridDim.x * blockDim.x) {
        int src, dst;
        load_edge(ei, is64, e, src, dst);
        if ((unsigned)dst < NN && (unsigned)src < NN) {
            int pos = atomicAdd(&g_cur[dst], 1);
            g_csr[pos] = src;
        }
    }
}

// ---- helper: accumulate one fp16 chunk (4 halves) into fp32 sums ----
__device__ __forceinline__ void acc4(uint2 v, float& sx, float& sy,
                                     float& sz, float& sw) {
    float2 fa = __half22float2(u2h(v.x));
    float2 fb = __half22float2(u2h(v.y));
    sx += fa.x; sy += fa.y; sz += fb.x; sw += fb.y;
}

// ---- 5) propagation layer. FUSE=1: layer 3 + final combine fused.
//         Warp per node, lane handles 4 dims. Depth-2 HADD2 tree per 4 edges. ----
template<int FUSE>
__global__ void k_layer_t(int in_idx, float4* __restrict__ out4) {
    const uint2* __restrict__ in = g_h[in_idx];

    int warp = (blockIdx.x * blockDim.x + threadIdx.x) >> 5;
    if (warp >= NN) return;
    int lane = threadIdx.x & 31;

    int beg = g_off[warp];
    int end = g_off[warp + 1];

    float sx = 0.f, sy = 0.f, sz = 0.f, sw = 0.f;
    int e = beg;
    for (; e + 3 < end; e += 4) {
        int s0 = g_csr[e];
        int s1 = g_csr[e + 1];
        int s2 = g_csr[e + 2];
        int s3 = g_csr[e + 3];
        uint2 v0 = in[(size_t)s0 * D4 + lane];
        uint2 v1 = in[(size_t)s1 * D4 + lane];
        uint2 v2 = in[(size_t)s2 * D4 + lane];
        uint2 v3 = in[(size_t)s3 * D4 + lane];
        // depth-2 fp16 tree, one fp32 accumulate per 4 edges
        __half2 a = __hadd2(__hadd2(u2h(v0.x), u2h(v1.x)),
                            __hadd2(u2h(v2.x), u2h(v3.x)));
        __half2 b = __hadd2(__hadd2(u2h(v0.y), u2h(v1.y)),
                            __hadd2(u2h(v2.y), u2h(v3.y)));
        float2 fa = __half22float2(a);
        float2 fb = __half22float2(b);
        sx += fa.x; sy += fa.y; sz += fb.x; sw += fb.y;
    }
    for (; e < end; ++e) {                      // tail: exact fp32 adds
        int s = g_csr[e];
        acc4(in[(size_t)s * D4 + lane], sx, sy, sz, sw);
    }

    float idg = g_inv[warp];
    float rx = sx * idg, ry = sy * idg, rz = sz * idg, rw = sw * idg;

    size_t oi = (size_t)warp * D4 + lane;
    if (FUSE) {
        // out = (x + a1 + a2 + a3) / 4 ; x from fp16 g_h[0], a2 == in[oi],
        // a3 == r (registers). All fp16 reads, fp32 accumulate.
        float tx = rx, ty = ry, tz = rz, tw = rw;
        acc4(g_h[0][oi], tx, ty, tz, tw);
        acc4(g_h[1][oi], tx, ty, tz, tw);
        acc4(in[oi],     tx, ty, tz, tw);
        float4 r;
        r.x = tx * 0.25f; r.y = ty * 0.25f; r.z = tz * 0.25f; r.w = tw * 0.25f;
        out4[oi] = r;
    } else {
        __half2 ha = __floats2half2_rn(rx, ry);
        __half2 hb = __floats2half2_rn(rz, rw);
        uint2 o;
        o.x = *reinterpret_cast<unsigned*>(&ha);
        o.y = *reinterpret_cast<unsigned*>(&hb);
        g_h[in_idx + 1][oi] = o;
    }
}

extern "C" void kernel_launch(void* const* d_in, const int* in_sizes, int n_in,
                              void* d_out, int out_size) {
    const float4* u4  = (const float4*)d_in[0];
    const float4* i4  = (const float4*)d_in[1];
    const void*   ei  = d_in[2];
    float4*       out = (float4*)d_out;

    // CSR build: fused detect/zero/flag-reset, init, hist, one-shot scan, scatter
    k_detect_zero<<<(NN + 255) / 256, 256>>>((const int*)ei);
    k_init_emb<<<2048, 256>>>(u4, i4);
    k_hist<<<4096, 256>>>(ei);
    k_scan_fused<<<SCAN_NB, SCAN_B>>>();
    k_scatter<<<2048, 256>>>(ei);

    // 3 propagation layers (warp per node); layer 3 fused with final combine
    const int layer_blocks = (NN * 32 + 255) / 256;
    k_layer_t<0><<<layer_blocks, 256>>>(0, out);  // x  -> a1
    k_layer_t<0><<<layer_blocks, 256>>>(1, out);  // a1 -> a2
    k_layer_t<1><<<layer_blocks, 256>>>(2, out);  // a2 -> out (fused)
}